// round 10
// baseline (speedup 1.0000x reference)
#include <cuda_runtime.h>
#include <cuda_bf16.h>
#include <math.h>
#include <stdint.h>

#define B_   4
#define Q_   75
#define C_   640
#define M_   196
#define N_   5
#define KS_  5
#define BQ_  (B_*Q_)        // 300
#define MT_  115            // M tiles of 128 per batch (115*128 = 14720)
#define RPB  14720          // padded query rows per batch
#define NPAD 224            // padded ms per class
#define KC   32             // K chunk (bf16)
#define KT_  (C_/KC)        // 20

// smem stage layout (bytes), row stride 80B (40 bf16) => conflict-free ldmatrix
#define ROWB   80
#define AHI_O  0
#define ALO_O  10240
#define BHI_O  20480
#define BLO_O  29440
#define STAGEB 38400
#define SMEM_BYTES (2*STAGEB)

// ---------------- scratch (static device globals; zero-initialized) --------
__device__ __nv_bfloat16 g_qn_hi[(size_t)B_*RPB*C_];   // pad rows stay 0
__device__ __nv_bfloat16 g_qn_lo[(size_t)B_*RPB*C_];
__device__ __nv_bfloat16 g_sn_hi[B_*N_*NPAD*C_];       // pad rows 196..223 stay 0
__device__ __nv_bfloat16 g_sn_lo[B_*N_*NPAD*C_];
__device__ float g_rowmax[BQ_*N_*2*M_];
__device__ int   g_rowarg[BQ_*N_*2*M_];
__device__ float g_loss[BQ_];

// ---------------- PTX helpers ----------------------------------------------
__device__ __forceinline__ uint32_t s2u(const void* p) {
    uint32_t a;
    asm("{ .reg .u64 t; cvta.to.shared.u64 t, %1; cvt.u32.u64 %0, t; }"
        : "=r"(a) : "l"(p));
    return a;
}
__device__ __forceinline__ void cp16(uint32_t dst, const void* src) {
    asm volatile("cp.async.cg.shared.global [%0], [%1], 16;" :: "r"(dst), "l"(src));
}
__device__ __forceinline__ void ldsm4(uint32_t* r, uint32_t a) {
    asm volatile("ldmatrix.sync.aligned.m8n8.x4.shared.b16 {%0,%1,%2,%3}, [%4];"
                 : "=r"(r[0]), "=r"(r[1]), "=r"(r[2]), "=r"(r[3]) : "r"(a));
}
__device__ __forceinline__ void ldsm2(uint32_t* r, uint32_t a) {
    asm volatile("ldmatrix.sync.aligned.m8n8.x2.shared.b16 {%0,%1}, [%2];"
                 : "=r"(r[0]), "=r"(r[1]) : "r"(a));
}
__device__ __forceinline__ void mma16816(float* c, const uint32_t* a, const uint32_t* b) {
    asm volatile("mma.sync.aligned.m16n8k16.row.col.f32.bf16.bf16.f32 "
                 "{%0,%1,%2,%3}, {%4,%5,%6,%7}, {%8,%9}, {%0,%1,%2,%3};"
                 : "+f"(c[0]), "+f"(c[1]), "+f"(c[2]), "+f"(c[3])
                 : "r"(a[0]), "r"(a[1]), "r"(a[2]), "r"(a[3]), "r"(b[0]), "r"(b[1]));
}

__global__ void dummy_kernel() {}

// ---------------- fused prep: norm + transpose + split, L2-resident --------
// One block per entity (20 support class-means + 300 queries). Pass 1 reads
// the entity's full (C,M) slab for the norm; pass 2 re-reads it (L2-hot)
// tile-by-tile, transposes and writes split bf16. Numerics identical to the
// previous 3-kernel prep (same c/k accumulation order).
__global__ void __launch_bounds__(256)
prep_all(const float* __restrict__ sup, const float* __restrict__ qf) {
    int bid = blockIdx.x;
    int tid = threadIdx.x;
    __shared__ float rinv[M_];
    __shared__ float tile[32][201];      // padded: conflict-free column reads

    if (bid < B_*N_) {
        // -------- support class bn: k-shot mean + norm + transpose --------
        int bn = bid;
        const float* base = sup + (size_t)bn * KS_ * C_ * M_;

        if (tid < M_) {
            float s = 0.f;
            for (int c = 0; c < C_; c++) {
                float v = 0.f;
                #pragma unroll
                for (int k = 0; k < KS_; k++) v += base[(size_t)k*C_*M_ + c*M_ + tid];
                v *= 0.2f;
                s += v*v;
            }
            rinv[tid] = 1.0f / fmaxf(sqrtf(s), 1e-8f);
        }
        __syncthreads();

        size_t ob = (size_t)bn * NPAD * C_;
        for (int tc = 0; tc < C_/32; tc++) {
            for (int idx = tid; idx < 32*M_; idx += 256) {
                int cc = idx / M_, m = idx - cc*M_;
                float v = 0.f;
                #pragma unroll
                for (int k = 0; k < KS_; k++)
                    v += base[(size_t)k*C_*M_ + (size_t)(tc*32 + cc)*M_ + m];
                tile[cc][m] = v * 0.2f;
            }
            __syncthreads();
            for (int idx = tid; idx < M_*32; idx += 256) {
                int m = idx >> 5, cc = idx & 31;     // warp: fixed m, cc 0..31
                float v = tile[cc][m] * rinv[m];
                __nv_bfloat16 h = __float2bfloat16(v);
                size_t o = ob + (size_t)m*C_ + tc*32 + cc;
                g_sn_hi[o] = h;
                g_sn_lo[o] = __float2bfloat16(v - __bfloat162float(h));
            }
            __syncthreads();
        }
    } else {
        // -------- query bq: norm + transpose --------
        int bq = bid - B_*N_;
        int b = bq / Q_, q = bq % Q_;
        const float* in = qf + (size_t)bq * C_ * M_;

        if (tid < M_) {
            float s = 0.f;
            for (int c = 0; c < C_; c++) { float v = in[c*M_ + tid]; s += v*v; }
            rinv[tid] = 1.0f / fmaxf(sqrtf(s), 1e-8f);
        }
        __syncthreads();

        size_t rowbase = (size_t)b * RPB + (size_t)q * M_;
        for (int tc = 0; tc < C_/32; tc++) {
            for (int idx = tid; idx < 32*M_; idx += 256) {
                int cc = idx / M_, m = idx - cc*M_;
                tile[cc][m] = in[(size_t)(tc*32 + cc)*M_ + m];
            }
            __syncthreads();
            for (int idx = tid; idx < M_*32; idx += 256) {
                int m = idx >> 5, cc = idx & 31;
                float v = tile[cc][m] * rinv[m];
                __nv_bfloat16 h = __float2bfloat16(v);
                size_t o = (rowbase + m)*C_ + tc*32 + cc;
                g_qn_hi[o] = h;
                g_qn_lo[o] = __float2bfloat16(v - __bfloat162float(h));
            }
            __syncthreads();
        }
    }
}

// ---------------- HMMA GEMM (split-bf16 x3) + row max/argmax epilogue -------
// (identical to the validated 671 us kernel)
__global__ void __launch_bounds__(256)
gemm_hmma() {
    int nh = blockIdx.x;             // n*2 + half  (fastest: A-tile L2 reuse)
    int n = nh >> 1, half = nh & 1;
    int mt = blockIdx.y, b = blockIdx.z;

    extern __shared__ char dynsm[];
    uint32_t sbase = s2u(dynsm);

    int tid = threadIdx.x, lane = tid & 31, wid = tid >> 5;
    int wr = wid >> 1, wc = wid & 1;

    const size_t arbase = (size_t)b * RPB + (size_t)mt * 128;
    const size_t brbase = (size_t)(b*N_ + n) * NPAD + (size_t)half * 112;

    float acc[2][7][4];
    #pragma unroll
    for (int i = 0; i < 2; i++)
        #pragma unroll
        for (int j = 0; j < 7; j++)
            #pragma unroll
            for (int p = 0; p < 4; p++) acc[i][j][p] = 0.f;

    auto issue = [&](int stage, int kt) {
        uint32_t so = sbase + stage * STAGEB;
        for (int i = tid; i < 512; i += 256) {        // A: 128 rows x 4 chunks
            int r = i >> 2, c = i & 3;
            size_t go = (arbase + r) * C_ + kt*KC + c*8;
            uint32_t ds = so + r*ROWB + c*16;
            cp16(ds + AHI_O, g_qn_hi + go);
            cp16(ds + ALO_O, g_qn_lo + go);
        }
        for (int i = tid; i < 448; i += 256) {        // B: 112 rows x 4 chunks
            int r = i >> 2, c = i & 3;
            size_t go = (brbase + r) * C_ + kt*KC + c*8;
            uint32_t ds = so + BHI_O + r*ROWB + c*16;
            cp16(ds, g_sn_hi + go);
            cp16(ds + (BLO_O - BHI_O), g_sn_lo + go);
        }
        asm volatile("cp.async.commit_group;" ::: "memory");
    };

    issue(0, 0);

    #pragma unroll 1
    for (int kt = 0; kt < KT_; kt++) {
        if (kt + 1 < KT_) {
            issue((kt + 1) & 1, kt + 1);
            asm volatile("cp.async.wait_group 1;" ::: "memory");
        } else {
            asm volatile("cp.async.wait_group 0;" ::: "memory");
        }
        __syncthreads();

        uint32_t so = sbase + (kt & 1) * STAGEB;

        uint32_t Ahi[2][2][4], Alo[2][2][4];
        #pragma unroll
        for (int i = 0; i < 2; i++)
            #pragma unroll
            for (int ks = 0; ks < 2; ks++) {
                int row = wr*32 + i*16 + (lane & 7) + ((lane >> 3) & 1) * 8;
                int col = ks*16 + ((lane >> 4) & 1) * 8;
                uint32_t ad = so + row*ROWB + col*2;
                ldsm4(Ahi[i][ks], ad + AHI_O);
                ldsm4(Alo[i][ks], ad + ALO_O);
            }

        #pragma unroll
        for (int j = 0; j < 7; j++) {
            uint32_t Bhi[2][2], Blo[2][2];
            #pragma unroll
            for (int ks = 0; ks < 2; ks++) {
                int row = wc*56 + j*8 + (lane & 7);
                int col = ks*16 + ((lane >> 3) & 1) * 8;
                uint32_t bd = so + BHI_O + row*ROWB + col*2;
                ldsm2(Bhi[ks], bd);
                ldsm2(Blo[ks], bd + (BLO_O - BHI_O));
            }
            #pragma unroll
            for (int ks = 0; ks < 2; ks++)
                #pragma unroll
                for (int i = 0; i < 2; i++) {
                    mma16816(acc[i][j], Ahi[i][ks], Bhi[ks]);
                    mma16816(acc[i][j], Ahi[i][ks], Blo[ks]);
                    mma16816(acc[i][j], Alo[i][ks], Bhi[ks]);
                }
        }
        __syncthreads();
    }

    float* sv = (float*)dynsm;            // [2][128]
    int*   sc = (int*)(dynsm + 1024);     // [2][128]

    int rq = lane >> 2, cq = lane & 3;
    #pragma unroll
    for (int i = 0; i < 2; i++) {
        #pragma unroll
        for (int rh = 0; rh < 2; rh++) {
            float bv = -1e30f; int bc = 0x7fffffff;
            #pragma unroll
            for (int j = 0; j < 7; j++) {
                #pragma unroll
                for (int p = 0; p < 2; p++) {
                    int gc = half*112 + wc*56 + j*8 + cq*2 + p;
                    float v = acc[i][j][rh*2 + p];
                    if (gc < M_ && (v > bv || (v == bv && gc < bc))) { bv = v; bc = gc; }
                }
            }
            #pragma unroll
            for (int off = 1; off < 4; off <<= 1) {
                float ov = __shfl_xor_sync(0xffffffffu, bv, off);
                int   oc = __shfl_xor_sync(0xffffffffu, bc, off);
                if (ov > bv || (ov == bv && oc < bc)) { bv = ov; bc = oc; }
            }
            if (cq == 0) {
                int rl = wr*32 + i*16 + rh*8 + rq;      // CTA-local row 0..127
                sv[wc*128 + rl] = bv;
                sc[wc*128 + rl] = bc;
            }
        }
    }
    __syncthreads();

    if (tid < 128) {
        float v0 = sv[tid],       v1 = sv[128 + tid];
        int   c0 = sc[tid],       c1 = sc[128 + tid];
        float bv; int bc;
        if (v1 > v0) { bv = v1; bc = c1; } else { bv = v0; bc = c0; }
        int gr = mt*128 + tid;
        if (gr < Q_*M_) {
            int q = gr / M_, mq = gr % M_;
            int o = (((b*Q_ + q)*N_ + n)*2 + half)*M_ + mq;
            g_rowmax[o] = bv;
            g_rowarg[o] = bc;
        }
    }
}

// ---------------- per-(b,q) mutual-NN mask + predict + loss -----------------
__global__ void combine_kernel(const int* __restrict__ qy) {
    int bq = blockIdx.x;
    int tid = threadIdx.x;          // 256 threads

    __shared__ float rowm[N_][M_];
    __shared__ float bestv[M_];
    __shared__ int   bestj[M_];
    __shared__ int   maskf[M_];
    __shared__ float pred[N_];

    if (tid < M_) {
        float bv = -1e30f; int bj = 0;
        #pragma unroll
        for (int nn = 0; nn < N_; nn++) {
            int o0 = ((bq*N_ + nn)*2 + 0)*M_ + tid;
            int o1 = ((bq*N_ + nn)*2 + 1)*M_ + tid;
            float m0 = g_rowmax[o0]; int a0 = g_rowarg[o0];
            float m1 = g_rowmax[o1]; int a1 = g_rowarg[o1];
            float rv; int ra;
            if (m1 > m0) { rv = m1; ra = a1; } else { rv = m0; ra = a0; }
            rowm[nn][tid] = rv;
            if (rv > bv) { bv = rv; bj = nn*M_ + ra; }   // ascending n: first occurrence
        }
        bestv[tid] = bv; bestj[tid] = bj;
    }
    __syncthreads();

    if (tid < M_) {
        float v = bestv[tid]; int j = bestj[tid];
        int ok = (v + 1.0f) > 0.0f;
        for (int t = 0; t < M_; t++) {
            if (t == tid) continue;
            if (bestj[t] == j) {
                float vt = bestv[t];
                if (vt > v || (vt == v && t < tid)) ok = 0;
            }
        }
        maskf[tid] = ok;
    }
    __syncthreads();

    if (tid < N_) {                 // deterministic fixed-order sum
        float s = 0.f;
        for (int m = 0; m < M_; m++)
            if (maskf[m]) s += rowm[tid][m];
        pred[tid] = 2.0f * s;       // TEMPERATURE
    }
    __syncthreads();

    if (tid == 0) {
        float mx = pred[0];
        #pragma unroll
        for (int nn = 1; nn < N_; nn++) mx = fmaxf(mx, pred[nn]);
        float se = 0.f;
        #pragma unroll
        for (int nn = 0; nn < N_; nn++) se += expf(pred[nn] - mx);
        float lse = mx + logf(se);
        int y = qy[bq];
        g_loss[bq] = lse - pred[y];
    }
}

__global__ void final_kernel(float* __restrict__ out) {
    if (threadIdx.x == 0) {
        float s = 0.f;
        for (int i = 0; i < BQ_; i++) s += g_loss[i];
        out[0] = s / (float)BQ_;
    }
}

extern "C" void kernel_launch(void* const* d_in, const int* in_sizes, int n_in,
                              void* d_out, int out_size) {
    const float* sup = (const float*)d_in[0];
    // d_in[1] = support_y : unused by the reference computation
    const float* qf  = (const float*)d_in[2];
    const int*   qy  = (const int*)d_in[3];

    cudaFuncSetAttribute(gemm_hmma, cudaFuncAttributeMaxDynamicSharedMemorySize, SMEM_BYTES);

    prep_all<<<B_*N_ + BQ_, 256>>>(sup, qf);          // launch 0
    dummy_kernel<<<1, 32>>>();                        // launch 1 (slot padding)
    dummy_kernel<<<1, 32>>>();                        // launch 2 (slot padding)

    dim3 grid(N_*2, MT_, B_);   // nh fastest -> adjacent CTAs share A tile in L2
    gemm_hmma<<<grid, 256, SMEM_BYTES>>>();           // launch 3 (ncu slot)

    combine_kernel<<<BQ_, 256>>>(qy);
    final_kernel  <<<1, 32>>>((float*)d_out);
}

// round 11
// speedup vs baseline: 1.3809x; 1.3809x over previous
#include <cuda_runtime.h>
#include <cuda_bf16.h>
#include <math.h>
#include <stdint.h>

#define B_   4
#define Q_   75
#define C_   640
#define M_   196
#define N_   5
#define KS_  5
#define BQ_  (B_*Q_)        // 300
#define NE_  (B_*N_ + BQ_)  // 320 entities (20 support class-means + 300 queries)
#define MT_  115            // M tiles of 128 per batch (115*128 = 14720)
#define RPB  14720          // padded query rows per batch
#define NPAD 224            // padded ms per class
#define KC   32             // K chunk (bf16)
#define KT_  (C_/KC)        // 20

// smem stage layout (bytes), row stride 80B (40 bf16) => conflict-free ldmatrix
#define ROWB   80
#define AHI_O  0
#define ALO_O  10240
#define BHI_O  20480
#define BLO_O  29440
#define STAGEB 38400
#define SMEM_BYTES (2*STAGEB)

// ---------------- scratch (static device globals; zero-initialized) --------
__device__ __nv_bfloat16 g_qn_hi[(size_t)B_*RPB*C_];   // pad rows stay 0
__device__ __nv_bfloat16 g_qn_lo[(size_t)B_*RPB*C_];
__device__ __nv_bfloat16 g_sn_hi[B_*N_*NPAD*C_];       // pad rows 196..223 stay 0
__device__ __nv_bfloat16 g_sn_lo[B_*N_*NPAD*C_];
__device__ float g_part[NE_*20*M_];                    // per-(entity, ctile, m) sumsq
__device__ float g_rinv[NE_*M_];
__device__ float g_rowmax[BQ_*N_*2*M_];
__device__ int   g_rowarg[BQ_*N_*2*M_];
__device__ float g_loss[BQ_];

// ---------------- PTX helpers ----------------------------------------------
__device__ __forceinline__ uint32_t s2u(const void* p) {
    uint32_t a;
    asm("{ .reg .u64 t; cvta.to.shared.u64 t, %1; cvt.u32.u64 %0, t; }"
        : "=r"(a) : "l"(p));
    return a;
}
__device__ __forceinline__ void cp16(uint32_t dst, const void* src) {
    asm volatile("cp.async.cg.shared.global [%0], [%1], 16;" :: "r"(dst), "l"(src));
}
__device__ __forceinline__ void ldsm4(uint32_t* r, uint32_t a) {
    asm volatile("ldmatrix.sync.aligned.m8n8.x4.shared.b16 {%0,%1,%2,%3}, [%4];"
                 : "=r"(r[0]), "=r"(r[1]), "=r"(r[2]), "=r"(r[3]) : "r"(a));
}
__device__ __forceinline__ void ldsm2(uint32_t* r, uint32_t a) {
    asm volatile("ldmatrix.sync.aligned.m8n8.x2.shared.b16 {%0,%1}, [%2];"
                 : "=r"(r[0]), "=r"(r[1]) : "r"(a));
}
__device__ __forceinline__ void mma16816(float* c, const uint32_t* a, const uint32_t* b) {
    asm volatile("mma.sync.aligned.m16n8k16.row.col.f32.bf16.bf16.f32 "
                 "{%0,%1,%2,%3}, {%4,%5,%6,%7}, {%8,%9}, {%0,%1,%2,%3};"
                 : "+f"(c[0]), "+f"(c[1]), "+f"(c[2]), "+f"(c[3])
                 : "r"(a[0]), "r"(a[1]), "r"(a[2]), "r"(a[3]), "r"(b[0]), "r"(b[1]));
}

// ---------------- P0: per-(entity, ctile) partial sumsq ---------------------
__global__ void __launch_bounds__(256)
part_sumsq(const float* __restrict__ sup, const float* __restrict__ qf) {
    int tc = blockIdx.x;                 // 0..19 channel tile
    int e  = blockIdx.y;                 // 0..319 entity
    int tid = threadIdx.x;
    __shared__ float tile[32][201];      // padded: conflict-free columns

    if (e < B_*N_) {                     // support class-mean tile
        const float* base = sup + (size_t)e * KS_ * C_ * M_;
        for (int idx = tid; idx < 32*M_; idx += 256) {
            int cc = idx / M_, m = idx - cc*M_;
            float v = 0.f;
            #pragma unroll
            for (int k = 0; k < KS_; k++)
                v += base[(size_t)k*C_*M_ + (size_t)(tc*32 + cc)*M_ + m];
            tile[cc][m] = v * 0.2f;
        }
    } else {                             // query tile
        const float* in = qf + (size_t)(e - B_*N_) * C_ * M_;
        for (int idx = tid; idx < 32*M_; idx += 256) {
            int cc = idx / M_, m = idx - cc*M_;
            tile[cc][m] = in[(size_t)(tc*32 + cc)*M_ + m];
        }
    }
    __syncthreads();
    if (tid < M_) {
        float s = 0.f;
        #pragma unroll
        for (int cc = 0; cc < 32; cc++) { float v = tile[cc][tid]; s += v*v; }
        g_part[(e*20 + tc)*M_ + tid] = s;
    }
}

// ---------------- P1: fold 20 partials -> rinv ------------------------------
__global__ void rinv_k() {
    int e = blockIdx.x;
    int m = threadIdx.x;
    if (m < M_) {
        float s = 0.f;
        #pragma unroll
        for (int tc = 0; tc < 20; tc++) s += g_part[(e*20 + tc)*M_ + m];
        g_rinv[e*M_ + m] = 1.0f / fmaxf(sqrtf(s), 1e-8f);
    }
}

// ---------------- TR: transpose + scale + split (support & query) -----------
__global__ void __launch_bounds__(256)
tr_all(const float* __restrict__ sup, const float* __restrict__ qf) {
    int tc = blockIdx.x;                 // 0..19
    int e  = blockIdx.y;                 // 0..319
    int tid = threadIdx.x;
    __shared__ float tile[32][201];

    if (e < B_*N_) {
        int bn = e;
        const float* base = sup + (size_t)bn * KS_ * C_ * M_;
        for (int idx = tid; idx < 32*M_; idx += 256) {
            int cc = idx / M_, m = idx - cc*M_;
            float v = 0.f;
            #pragma unroll
            for (int k = 0; k < KS_; k++)
                v += base[(size_t)k*C_*M_ + (size_t)(tc*32 + cc)*M_ + m];
            tile[cc][m] = v * 0.2f;
        }
        __syncthreads();
        size_t ob = (size_t)bn * NPAD * C_;
        const float* rv = g_rinv + e*M_;
        for (int idx = tid; idx < M_*32; idx += 256) {
            int m = idx >> 5, cc = idx & 31;     // warp: fixed m, cc 0..31
            float v = tile[cc][m] * rv[m];
            __nv_bfloat16 h = __float2bfloat16(v);
            size_t o = ob + (size_t)m*C_ + tc*32 + cc;
            g_sn_hi[o] = h;
            g_sn_lo[o] = __float2bfloat16(v - __bfloat162float(h));
        }
    } else {
        int bq = e - B_*N_;
        int b = bq / Q_, q = bq % Q_;
        const float* in = qf + (size_t)bq * C_ * M_;
        for (int idx = tid; idx < 32*M_; idx += 256) {
            int cc = idx / M_, m = idx - cc*M_;
            tile[cc][m] = in[(size_t)(tc*32 + cc)*M_ + m];
        }
        __syncthreads();
        size_t rowbase = (size_t)b * RPB + (size_t)q * M_;
        const float* rv = g_rinv + e*M_;
        for (int idx = tid; idx < M_*32; idx += 256) {
            int m = idx >> 5, cc = idx & 31;
            float v = tile[cc][m] * rv[m];
            __nv_bfloat16 h = __float2bfloat16(v);
            size_t o = (rowbase + m)*C_ + tc*32 + cc;
            g_qn_hi[o] = h;
            g_qn_lo[o] = __float2bfloat16(v - __bfloat162float(h));
        }
    }
}

// ---------------- HMMA GEMM (split-bf16 x3) + row max/argmax epilogue -------
// (identical to the validated 668 us kernel)
__global__ void __launch_bounds__(256)
gemm_hmma() {
    int nh = blockIdx.x;             // n*2 + half  (fastest: A-tile L2 reuse)
    int n = nh >> 1, half = nh & 1;
    int mt = blockIdx.y, b = blockIdx.z;

    extern __shared__ char dynsm[];
    uint32_t sbase = s2u(dynsm);

    int tid = threadIdx.x, lane = tid & 31, wid = tid >> 5;
    int wr = wid >> 1, wc = wid & 1;

    const size_t arbase = (size_t)b * RPB + (size_t)mt * 128;
    const size_t brbase = (size_t)(b*N_ + n) * NPAD + (size_t)half * 112;

    float acc[2][7][4];
    #pragma unroll
    for (int i = 0; i < 2; i++)
        #pragma unroll
        for (int j = 0; j < 7; j++)
            #pragma unroll
            for (int p = 0; p < 4; p++) acc[i][j][p] = 0.f;

    auto issue = [&](int stage, int kt) {
        uint32_t so = sbase + stage * STAGEB;
        for (int i = tid; i < 512; i += 256) {        // A: 128 rows x 4 chunks
            int r = i >> 2, c = i & 3;
            size_t go = (arbase + r) * C_ + kt*KC + c*8;
            uint32_t ds = so + r*ROWB + c*16;
            cp16(ds + AHI_O, g_qn_hi + go);
            cp16(ds + ALO_O, g_qn_lo + go);
        }
        for (int i = tid; i < 448; i += 256) {        // B: 112 rows x 4 chunks
            int r = i >> 2, c = i & 3;
            size_t go = (brbase + r) * C_ + kt*KC + c*8;
            uint32_t ds = so + BHI_O + r*ROWB + c*16;
            cp16(ds, g_sn_hi + go);
            cp16(ds + (BLO_O - BHI_O), g_sn_lo + go);
        }
        asm volatile("cp.async.commit_group;" ::: "memory");
    };

    issue(0, 0);

    #pragma unroll 1
    for (int kt = 0; kt < KT_; kt++) {
        if (kt + 1 < KT_) {
            issue((kt + 1) & 1, kt + 1);
            asm volatile("cp.async.wait_group 1;" ::: "memory");
        } else {
            asm volatile("cp.async.wait_group 0;" ::: "memory");
        }
        __syncthreads();

        uint32_t so = sbase + (kt & 1) * STAGEB;

        uint32_t Ahi[2][2][4], Alo[2][2][4];
        #pragma unroll
        for (int i = 0; i < 2; i++)
            #pragma unroll
            for (int ks = 0; ks < 2; ks++) {
                int row = wr*32 + i*16 + (lane & 7) + ((lane >> 3) & 1) * 8;
                int col = ks*16 + ((lane >> 4) & 1) * 8;
                uint32_t ad = so + row*ROWB + col*2;
                ldsm4(Ahi[i][ks], ad + AHI_O);
                ldsm4(Alo[i][ks], ad + ALO_O);
            }

        #pragma unroll
        for (int j = 0; j < 7; j++) {
            uint32_t Bhi[2][2], Blo[2][2];
            #pragma unroll
            for (int ks = 0; ks < 2; ks++) {
                int row = wc*56 + j*8 + (lane & 7);
                int col = ks*16 + ((lane >> 3) & 1) * 8;
                uint32_t bd = so + BHI_O + row*ROWB + col*2;
                ldsm2(Bhi[ks], bd);
                ldsm2(Blo[ks], bd + (BLO_O - BHI_O));
            }
            #pragma unroll
            for (int ks = 0; ks < 2; ks++)
                #pragma unroll
                for (int i = 0; i < 2; i++) {
                    mma16816(acc[i][j], Ahi[i][ks], Bhi[ks]);
                    mma16816(acc[i][j], Ahi[i][ks], Blo[ks]);
                    mma16816(acc[i][j], Alo[i][ks], Bhi[ks]);
                }
        }
        __syncthreads();
    }

    float* sv = (float*)dynsm;            // [2][128]
    int*   sc = (int*)(dynsm + 1024);     // [2][128]

    int rq = lane >> 2, cq = lane & 3;
    #pragma unroll
    for (int i = 0; i < 2; i++) {
        #pragma unroll
        for (int rh = 0; rh < 2; rh++) {
            float bv = -1e30f; int bc = 0x7fffffff;
            #pragma unroll
            for (int j = 0; j < 7; j++) {
                #pragma unroll
                for (int p = 0; p < 2; p++) {
                    int gc = half*112 + wc*56 + j*8 + cq*2 + p;
                    float v = acc[i][j][rh*2 + p];
                    if (gc < M_ && (v > bv || (v == bv && gc < bc))) { bv = v; bc = gc; }
                }
            }
            #pragma unroll
            for (int off = 1; off < 4; off <<= 1) {
                float ov = __shfl_xor_sync(0xffffffffu, bv, off);
                int   oc = __shfl_xor_sync(0xffffffffu, bc, off);
                if (ov > bv || (ov == bv && oc < bc)) { bv = ov; bc = oc; }
            }
            if (cq == 0) {
                int rl = wr*32 + i*16 + rh*8 + rq;      // CTA-local row 0..127
                sv[wc*128 + rl] = bv;
                sc[wc*128 + rl] = bc;
            }
        }
    }
    __syncthreads();

    if (tid < 128) {
        float v0 = sv[tid],       v1 = sv[128 + tid];
        int   c0 = sc[tid],       c1 = sc[128 + tid];
        float bv; int bc;
        if (v1 > v0) { bv = v1; bc = c1; } else { bv = v0; bc = c0; }
        int gr = mt*128 + tid;
        if (gr < Q_*M_) {
            int q = gr / M_, mq = gr % M_;
            int o = (((b*Q_ + q)*N_ + n)*2 + half)*M_ + mq;
            g_rowmax[o] = bv;
            g_rowarg[o] = bc;
        }
    }
}

// ---------------- per-(b,q) mutual-NN mask + predict + loss -----------------
__global__ void combine_kernel(const int* __restrict__ qy) {
    int bq = blockIdx.x;
    int tid = threadIdx.x;          // 256 threads

    __shared__ float rowm[N_][M_];
    __shared__ float bestv[M_];
    __shared__ int   bestj[M_];
    __shared__ int   maskf[M_];
    __shared__ float pred[N_];

    if (tid < M_) {
        float bv = -1e30f; int bj = 0;
        #pragma unroll
        for (int nn = 0; nn < N_; nn++) {
            int o0 = ((bq*N_ + nn)*2 + 0)*M_ + tid;
            int o1 = ((bq*N_ + nn)*2 + 1)*M_ + tid;
            float m0 = g_rowmax[o0]; int a0 = g_rowarg[o0];
            float m1 = g_rowmax[o1]; int a1 = g_rowarg[o1];
            float rv; int ra;
            if (m1 > m0) { rv = m1; ra = a1; } else { rv = m0; ra = a0; }
            rowm[nn][tid] = rv;
            if (rv > bv) { bv = rv; bj = nn*M_ + ra; }   // ascending n: first occurrence
        }
        bestv[tid] = bv; bestj[tid] = bj;
    }
    __syncthreads();

    if (tid < M_) {
        float v = bestv[tid]; int j = bestj[tid];
        int ok = (v + 1.0f) > 0.0f;
        for (int t = 0; t < M_; t++) {
            if (t == tid) continue;
            if (bestj[t] == j) {
                float vt = bestv[t];
                if (vt > v || (vt == v && t < tid)) ok = 0;
            }
        }
        maskf[tid] = ok;
    }
    __syncthreads();

    if (tid < N_) {                 // deterministic fixed-order sum
        float s = 0.f;
        for (int m = 0; m < M_; m++)
            if (maskf[m]) s += rowm[tid][m];
        pred[tid] = 2.0f * s;       // TEMPERATURE
    }
    __syncthreads();

    if (tid == 0) {
        float mx = pred[0];
        #pragma unroll
        for (int nn = 1; nn < N_; nn++) mx = fmaxf(mx, pred[nn]);
        float se = 0.f;
        #pragma unroll
        for (int nn = 0; nn < N_; nn++) se += expf(pred[nn] - mx);
        float lse = mx + logf(se);
        int y = qy[bq];
        g_loss[bq] = lse - pred[y];
    }
}

__global__ void final_kernel(float* __restrict__ out) {
    __shared__ float part[32];
    int lane = threadIdx.x;
    float s = 0.f;
    for (int i = lane; i < BQ_; i += 32) s += g_loss[i];   // fixed ascending order
    part[lane] = s;
    __syncwarp();
    if (lane == 0) {
        float t = 0.f;
        #pragma unroll
        for (int w = 0; w < 32; w++) t += part[w];          // fixed ascending order
        out[0] = t / (float)BQ_;
    }
}

extern "C" void kernel_launch(void* const* d_in, const int* in_sizes, int n_in,
                              void* d_out, int out_size) {
    const float* sup = (const float*)d_in[0];
    // d_in[1] = support_y : unused by the reference computation
    const float* qf  = (const float*)d_in[2];
    const int*   qy  = (const int*)d_in[3];

    cudaFuncSetAttribute(gemm_hmma, cudaFuncAttributeMaxDynamicSharedMemorySize, SMEM_BYTES);

    part_sumsq<<<dim3(20, NE_), 256>>>(sup, qf);      // launch 0
    rinv_k    <<<NE_, 224>>>();                       // launch 1
    tr_all    <<<dim3(20, NE_), 256>>>(sup, qf);      // launch 2

    dim3 grid(N_*2, MT_, B_);   // nh fastest -> adjacent CTAs share A tile in L2
    gemm_hmma<<<grid, 256, SMEM_BYTES>>>();           // launch 3 (ncu slot)

    combine_kernel<<<BQ_, 256>>>(qy);
    final_kernel  <<<1, 32>>>((float*)d_out);
}